// round 13
// baseline (speedup 1.0000x reference)
#include <cuda_runtime.h>
#include <math.h>

#define BATCH 128
#define TSEQ  1024
#define DIN   128
#define HID   256
#define FOURH 1024
#define DOUT  1000
#define NCTA  128
#define HB    (HID * BATCH)

// Scratch (device globals: allocation-free)
__device__ float d_xT[(size_t)TSEQ * DIN * BATCH];     // [t][k][b]  64 MB
__device__ float d_h1[2 * HB];                          // ping-pong [parity][j][b]
__device__ float d_h2[2 * HB];
__device__ int   g_cnt;

typedef unsigned long long ull;

__device__ __forceinline__ ull pack2(float lo, float hi) {
    ull r; asm("mov.b64 %0, {%1, %2};" : "=l"(r) : "f"(lo), "f"(hi)); return r;
}
__device__ __forceinline__ ull bcast2(float v) {
    ull r; asm("mov.b64 %0, {%1, %1};" : "=l"(r) : "f"(v)); return r;
}
__device__ __forceinline__ void upk(ull v, float& lo, float& hi) {
    asm("mov.b64 {%0, %1}, %2;" : "=f"(lo), "=f"(hi) : "l"(v));
}
__device__ __forceinline__ void ffma2(ull& d, ull a, ull b) {
    asm("fma.rn.f32x2 %0, %1, %2, %0;" : "+l"(d) : "l"(a), "l"(b));
}
__device__ __forceinline__ float sigmoidf(float z) {
    return __fdividef(1.0f, 1.0f + __expf(-z));
}

// ---------------------------------------------------------------------------
// Kernel 1: transpose x [B][T][D] -> d_xT [T][D][B]; zero state + counter.
// ---------------------------------------------------------------------------
__global__ void transpose_x_kernel(const float* __restrict__ x) {
    __shared__ float tile[32][129];
    const int t  = blockIdx.x;
    const int b0 = blockIdx.y * 32;
    if (blockIdx.y == 0) {
        int i = blockIdx.x * 256 + threadIdx.x;
        if (i < 2 * HB) { d_h1[i] = 0.0f; d_h2[i] = 0.0f; }
        if (blockIdx.x == 0 && threadIdx.x == 0) g_cnt = 0;
    }
    for (int idx = threadIdx.x; idx < 32 * 128; idx += 256) {
        int r = idx >> 7, k = idx & 127;
        tile[r][k] = x[(size_t)(b0 + r) * (TSEQ * DIN) + (size_t)t * DIN + k];
    }
    __syncthreads();
    for (int idx = threadIdx.x; idx < 32 * 128; idx += 256) {
        int k = idx >> 5, bb = idx & 31;
        d_xT[((size_t)t * DIN + k) * BATCH + b0 + bb] = tile[bb][k];
    }
}

// ---------------------------------------------------------------------------
// x-part: 16 k of x@W1 for batches {lane, lane+32, lane+64, lane+96}.
// Runs in the barrier shadow; xacc[a][p] overwritten.
// ---------------------------------------------------------------------------
__device__ __forceinline__ void compute_x(
    const float* __restrict__ xp, const ull (* __restrict__ sW1)[4],
    int kx, ull (&xacc)[4][4])
{
#pragma unroll
    for (int a = 0; a < 4; ++a)
#pragma unroll
        for (int p = 0; p < 4; ++p) xacc[a][p] = 0;
#pragma unroll 4
    for (int j = 0; j < 16; ++j) {
        float x0 = __ldcg(xp + j * BATCH);
        float x1 = __ldcg(xp + j * BATCH + 32);
        float x2 = __ldcg(xp + j * BATCH + 64);
        float x3 = __ldcg(xp + j * BATCH + 96);
        const int k = kx + j;
        ulonglong2 wa = *(const ulonglong2*)&sW1[k][0];
        ulonglong2 wb = *(const ulonglong2*)&sW1[k][2];
        ull v;
        v = bcast2(x0);
        ffma2(xacc[0][0], wa.x, v); ffma2(xacc[0][1], wa.y, v);
        ffma2(xacc[0][2], wb.x, v); ffma2(xacc[0][3], wb.y, v);
        v = bcast2(x1);
        ffma2(xacc[1][0], wa.x, v); ffma2(xacc[1][1], wa.y, v);
        ffma2(xacc[1][2], wb.x, v); ffma2(xacc[1][3], wb.y, v);
        v = bcast2(x2);
        ffma2(xacc[2][0], wa.x, v); ffma2(xacc[2][1], wa.y, v);
        ffma2(xacc[2][2], wb.x, v); ffma2(xacc[2][3], wb.y, v);
        v = bcast2(x3);
        ffma2(xacc[3][0], wa.x, v); ffma2(xacc[3][1], wa.y, v);
        ffma2(xacc[3][2], wb.x, v); ffma2(xacc[3][3], wb.y, v);
    }
}

// ---------------------------------------------------------------------------
// Kernel 2: persistent 2-layer LSTM + fused dense/softmax.
// 128 CTAs x 256 threads (8 warps). CTA owns units {2*cta, 2*cta+1}.
// Dot: warp = one k-slice (s = tid>>5, 32 hidden k / 16 x k); thread covers
// batches {lane, lane+32, lane+64, lane+96} -> each weight row is loaded by
// exactly ONE warp (halves weight-LDS wavefronts vs 512-thread layout), and
// each LDS.128 feeds 4x FFMA2. Layer-2: W2.h1 + U2.h2 merged in-loop.
// Epilogue: thread (eb=tid&127, eu=tid>>7) owns BOTH layers' c-state.
// Grid barrier every iteration; one warp polls; x@W1(t+1) in the shadow.
// ---------------------------------------------------------------------------
__global__ void __launch_bounds__(256, 1)
lstm_persistent(const float* __restrict__ W1, const float* __restrict__ U1,
                const float* __restrict__ b1, const float* __restrict__ W2,
                const float* __restrict__ U2, const float* __restrict__ b2,
                const float* __restrict__ Wd, const float* __restrict__ bd,
                float* __restrict__ out) {
    extern __shared__ __align__(16) char dyn[];
    ull (*sU1)[4] = (ull (*)[4])dyn;            // 256 rows
    ull (*sW2)[4] = sU1 + 256;                  // 256 rows
    ull (*sU2)[4] = sW2 + 256;                  // 256 rows
    ull (*sW1)[4] = sU2 + 256;                  // 128 rows
    ulonglong2* red = (ulonglong2*)(sW1 + 128); // [2 streams][2 pairs][8 s][128 slots]
#define RED2(st, pp, ss, bbx) red[((((st) << 1) + (pp)) << 10) + ((ss) << 7) + (bbx)]

    const int tid  = threadIdx.x;
    const int lane = tid & 31;
    const int s    = tid >> 5;         // k-slice 0..7 (one warp each)
    const int u0   = 2 * blockIdx.x;

    // Pack weights: column pairs -> 64-bit words.
    if (tid < 256) {
        int k = tid;
#pragma unroll
        for (int p = 0; p < 4; ++p) {
            int cA = 2 * p, cB = 2 * p + 1;
            int gcA = (cA & 3) * HID + u0 + (cA >> 2);
            int gcB = (cB & 3) * HID + u0 + (cB >> 2);
            sU1[k][p] = pack2(U1[k * FOURH + gcA], U1[k * FOURH + gcB]);
            sW2[k][p] = pack2(W2[k * FOURH + gcA], W2[k * FOURH + gcB]);
            sU2[k][p] = pack2(U2[k * FOURH + gcA], U2[k * FOURH + gcB]);
            if (k < 128)
                sW1[k][p] = pack2(W1[k * FOURH + gcA], W1[k * FOURH + gcB]);
        }
    }

    // Epilogue identity + biases + owned cell states (BOTH layers)
    const int eb = tid & 127;
    const int eu = tid >> 7;
    float EB1[4], EB2[4];
#pragma unroll
    for (int g = 0; g < 4; ++g) {
        int gc = g * HID + u0 + eu;
        EB1[g] = b1[gc];
        EB2[g] = b2[gc];
    }
    float c1 = 0.0f, c2 = 0.0f;
    __syncthreads();

    const int kh = 32 * s;   // hidden k base
    const int kx = 16 * s;   // x k base

    ull xacc[4][4];
    compute_x(d_xT + kx * BATCH + lane, sW1, kx, xacc);

    for (int iter = 0; iter <= TSEQ; ++iter) {
        const int rp = iter & 1, wp = rp ^ 1;
        const float* __restrict__ hp1 = d_h1 + rp * HB + kh * BATCH + lane;
        const float* __restrict__ hp2 = d_h2 + rp * HB + kh * BATCH + lane;

        ull a1[4][4], a2[4][4];
#pragma unroll
        for (int a = 0; a < 4; ++a)
#pragma unroll
            for (int p = 0; p < 4; ++p) { a1[a][p] = xacc[a][p]; a2[a][p] = 0; }

        // ---- hidden part (32 k), 4-k double-buffered pipeline ----
        {
            float H1a[4][4], H2a[4][4], H1b[4][4], H2b[4][4];
#pragma unroll
            for (int j = 0; j < 4; ++j)
#pragma unroll
                for (int a = 0; a < 4; ++a) {
                    H1a[j][a] = __ldcg(hp1 + j * BATCH + 32 * a);
                    H2a[j][a] = __ldcg(hp2 + j * BATCH + 32 * a);
                }
#pragma unroll
            for (int blk = 0; blk < 8; ++blk) {
                float (*c1h)[4] = (blk & 1) ? H1b : H1a;
                float (*c2h)[4] = (blk & 1) ? H2b : H2a;
                float (*n1h)[4] = (blk & 1) ? H1a : H1b;
                float (*n2h)[4] = (blk & 1) ? H2a : H2b;
                if (blk < 7) {
                    const int kn = (blk + 1) * 4;
#pragma unroll
                    for (int j = 0; j < 4; ++j)
#pragma unroll
                        for (int a = 0; a < 4; ++a) {
                            n1h[j][a] = __ldcg(hp1 + (kn + j) * BATCH + 32 * a);
                            n2h[j][a] = __ldcg(hp2 + (kn + j) * BATCH + 32 * a);
                        }
                }
#pragma unroll
                for (int j = 0; j < 4; ++j) {
                    const int k = kh + blk * 4 + j;
                    ulonglong2 wa = *(const ulonglong2*)&sU1[k][0];
                    ulonglong2 wb = *(const ulonglong2*)&sU1[k][2];
#pragma unroll
                    for (int a = 0; a < 4; ++a) {
                        ull v = bcast2(c1h[j][a]);
                        ffma2(a1[a][0], wa.x, v); ffma2(a1[a][1], wa.y, v);
                        ffma2(a1[a][2], wb.x, v); ffma2(a1[a][3], wb.y, v);
                    }
                    wa = *(const ulonglong2*)&sW2[k][0];
                    wb = *(const ulonglong2*)&sW2[k][2];
#pragma unroll
                    for (int a = 0; a < 4; ++a) {
                        ull v = bcast2(c1h[j][a]);
                        ffma2(a2[a][0], wa.x, v); ffma2(a2[a][1], wa.y, v);
                        ffma2(a2[a][2], wb.x, v); ffma2(a2[a][3], wb.y, v);
                    }
                    wa = *(const ulonglong2*)&sU2[k][0];
                    wb = *(const ulonglong2*)&sU2[k][2];
#pragma unroll
                    for (int a = 0; a < 4; ++a) {
                        ull v = bcast2(c2h[j][a]);
                        ffma2(a2[a][0], wa.x, v); ffma2(a2[a][1], wa.y, v);
                        ffma2(a2[a][2], wb.x, v); ffma2(a2[a][3], wb.y, v);
                    }
                }
            }
        }

        // ---- publish slice partials (slot = batch; lanes consecutive) ----
#pragma unroll
        for (int a = 0; a < 4; ++a) {
            const int bx = lane + 32 * a;
            RED2(0, 0, s, bx) = make_ulonglong2(a1[a][0], a1[a][1]);
            RED2(0, 1, s, bx) = make_ulonglong2(a1[a][2], a1[a][3]);
            RED2(1, 0, s, bx) = make_ulonglong2(a2[a][0], a2[a][1]);
            RED2(1, 1, s, bx) = make_ulonglong2(a2[a][2], a2[a][3]);
        }
        __syncthreads();   // publishes visible to epilogue

        // ---- epilogue: thread (eb, eu) handles BOTH layers ----
        if (iter < TSEQ) {
            float z0 = 0.f, z1 = 0.f, z2 = 0.f, z3 = 0.f, t0, t1;
#pragma unroll
            for (int s2 = 0; s2 < 8; ++s2) {
                ulonglong2 v = RED2(0, eu, s2, eb);
                upk(v.x, t0, t1); z0 += t0; z1 += t1;
                upk(v.y, t0, t1); z2 += t0; z3 += t1;
            }
            float ig = sigmoidf(z0 + EB1[0]);
            float fg = sigmoidf(z1 + EB1[1]);
            float gv = fmaxf(z2 + EB1[2], 0.f);
            float og = sigmoidf(z3 + EB1[3]);
            c1 = fg * c1 + ig * gv;
            __stcg(&d_h1[wp * HB + (u0 + eu) * BATCH + eb], og * fmaxf(c1, 0.f));
        }
        if (iter >= 1) {
            float z0 = 0.f, z1 = 0.f, z2 = 0.f, z3 = 0.f, t0, t1;
#pragma unroll
            for (int s2 = 0; s2 < 8; ++s2) {
                ulonglong2 v = RED2(1, eu, s2, eb);
                upk(v.x, t0, t1); z0 += t0; z1 += t1;
                upk(v.y, t0, t1); z2 += t0; z3 += t1;
            }
            float ig = sigmoidf(z0 + EB2[0]);
            float fg = sigmoidf(z1 + EB2[1]);
            float gv = fmaxf(z2 + EB2[2], 0.f);
            float og = sigmoidf(z3 + EB2[3]);
            c2 = fg * c2 + ig * gv;
            __stcg(&d_h2[wp * HB + (u0 + eu) * BATCH + eb], og * fmaxf(c2, 0.f));
        }
        __syncthreads();   // h stores issued + RED reads complete

        // ---- grid barrier: arrive once; ONE warp polls; sync releases CTA ----
        if (tid == 0) {
            asm volatile("red.release.gpu.global.add.s32 [%0], 1;"
                         :: "l"(&g_cnt) : "memory");
        }
        // x-part for the next step in the barrier shadow
        if (iter < TSEQ) {
            const int tn = (iter + 1 < TSEQ) ? (iter + 1) : (TSEQ - 1);
            compute_x(d_xT + (size_t)tn * (DIN * BATCH) + kx * BATCH + lane,
                      sW1, kx, xacc);
        }
        if (tid < 32) {
            const int tgt = NCTA * (iter + 1);
            int v;
            do {
                asm volatile("ld.acquire.gpu.global.s32 %0, [%1];"
                             : "=r"(v) : "l"(&g_cnt));
            } while (v < tgt);
        }
        __syncthreads();
    }

    // ---------------- Dense + softmax (CTA = one batch row) ----------------
    {
        const int brow = blockIdx.x;
        float* shh = (float*)red;          // [256] h
        float* rb  = shh + 256;            // [8] warp partials

        shh[tid] = __ldcg(&d_h2[HB + tid * BATCH + brow]);
        __syncthreads();

        float acc[4];
#pragma unroll
        for (int q = 0; q < 4; ++q) {
            int o = tid + 256 * q;
            acc[q] = (o < DOUT) ? bd[o] : -1e30f;
        }
#pragma unroll 8
        for (int k = 0; k < HID; ++k) {
            float h = shh[k];
            const float* wrow = Wd + (size_t)k * DOUT;
#pragma unroll
            for (int q = 0; q < 4; ++q) {
                int o = tid + 256 * q;
                if (o < DOUT) acc[q] += h * wrow[o];
            }
        }
        float lmax = fmaxf(fmaxf(acc[0], acc[1]), fmaxf(acc[2], acc[3]));
#pragma unroll
        for (int off = 16; off; off >>= 1)
            lmax = fmaxf(lmax, __shfl_xor_sync(0xffffffffu, lmax, off));
        if (lane == 0) rb[tid >> 5] = lmax;
        __syncthreads();
        if (tid == 0) {
            float m = rb[0];
#pragma unroll
            for (int i = 1; i < 8; ++i) m = fmaxf(m, rb[i]);
            rb[0] = m;
        }
        __syncthreads();
        const float M = rb[0];
        __syncthreads();

        float e[4];
        float lsum = 0.f;
#pragma unroll
        for (int q = 0; q < 4; ++q) {
            int o = tid + 256 * q;
            e[q] = (o < DOUT) ? __expf(acc[q] - M) : 0.f;
            lsum += e[q];
        }
#pragma unroll
        for (int off = 16; off; off >>= 1)
            lsum += __shfl_xor_sync(0xffffffffu, lsum, off);
        if (lane == 0) rb[tid >> 5] = lsum;
        __syncthreads();
        if (tid == 0) {
            float sm = 0.f;
#pragma unroll
            for (int i = 0; i < 8; ++i) sm += rb[i];
            rb[0] = sm;
        }
        __syncthreads();
        const float inv = __fdividef(1.0f, rb[0]);
#pragma unroll
        for (int q = 0; q < 4; ++q) {
            int o = tid + 256 * q;
            if (o < DOUT) out[(size_t)brow * DOUT + o] = e[q] * inv;
        }
    }
}

// ---------------------------------------------------------------------------
static const int SMEM_BYTES = (256 * 3 + 128) * 4 * 8 /*weights 28,672*/ +
                              2 * 2 * 8 * 128 * 16 /*red 65,536*/;  // 94,208

extern "C" void kernel_launch(void* const* d_in, const int* in_sizes, int n_in,
                              void* d_out, int out_size) {
    const float* x  = (const float*)d_in[0];
    const float* W1 = (const float*)d_in[1];
    const float* U1 = (const float*)d_in[2];
    const float* b1 = (const float*)d_in[3];
    const float* W2 = (const float*)d_in[4];
    const float* U2 = (const float*)d_in[5];
    const float* b2 = (const float*)d_in[6];
    const float* Wd = (const float*)d_in[7];
    const float* bd = (const float*)d_in[8];
    float* out = (float*)d_out;

    cudaFuncSetAttribute(lstm_persistent,
                         cudaFuncAttributeMaxDynamicSharedMemorySize,
                         SMEM_BYTES);

    transpose_x_kernel<<<dim3(TSEQ, 4), 256>>>(x);
    lstm_persistent<<<NCTA, 256, SMEM_BYTES>>>(W1, U1, b1, W2, U2, b2,
                                               Wd, bd, out);
}